// round 13
// baseline (speedup 1.0000x reference)
#include <cuda_runtime.h>
#include <cuda_fp16.h>
#include <cstdint>

#define NN 4096
#define HID 256
#define NHEADS 8
#define HEADD 32
#define EXS 0.2550390270190456f   // (1/sqrt(32)) * log2(e)

// ---------------- scratch (static device globals; no allocation) ----------------
__device__ __half   g_q[NHEADS][NN][HEADD];     // fp16 q, head-major
__device__ __half   g_v[NHEADS][NN][HEADD];     // fp16 v, head-major
__device__ __half   g_xh[NN * HID];             // fp16 x
__device__ __half   g_wqh[HID * HID];
__device__ __half   g_wvh[HID * HID];
__device__ __half   g_woh[HID * HID];
__device__ __half   g_obh[NN * HID];            // fp16 normalized attn@v
__device__ float    g_inv[NHEADS][NN];          // 1/rowsum
__device__ unsigned g_mask[NN][NN / 32];        // Adj packed to bits

// ---------------- helpers ----------------
__device__ __forceinline__ uint32_t smem_u32(const void* p) {
    uint32_t a;
    asm("{ .reg .u64 t; cvta.to.shared.u64 t, %1; cvt.u32.u64 %0, t; }" : "=r"(a) : "l"(p));
    return a;
}
__device__ __forceinline__ float ex2f(float x) {
    float y;
    asm("ex2.approx.f32 %0, %1;" : "=f"(y) : "f"(x));
    return y;
}
__device__ __forceinline__ void mma_f16(float c[4],
                                        unsigned a0, unsigned a1, unsigned a2, unsigned a3,
                                        unsigned b0, unsigned b1) {
    asm volatile(
        "mma.sync.aligned.m16n8k16.row.col.f32.f16.f16.f32 "
        "{%0,%1,%2,%3},{%4,%5,%6,%7},{%8,%9},{%0,%1,%2,%3};\n"
        : "+f"(c[0]), "+f"(c[1]), "+f"(c[2]), "+f"(c[3])
        : "r"(a0), "r"(a1), "r"(a2), "r"(a3), "r"(b0), "r"(b1));
}
#define LDSM_X4(d, addr) \
    asm volatile("ldmatrix.sync.aligned.m8n8.x4.shared.b16 {%0,%1,%2,%3}, [%4];" \
        : "=r"((d)[0]), "=r"((d)[1]), "=r"((d)[2]), "=r"((d)[3]) : "r"(addr))
#define LDSM_X4T(d, addr) \
    asm volatile("ldmatrix.sync.aligned.m8n8.x4.trans.shared.b16 {%0,%1,%2,%3}, [%4];" \
        : "=r"((d)[0]), "=r"((d)[1]), "=r"((d)[2]), "=r"((d)[3]) : "r"(addr))
__device__ __forceinline__ unsigned h2u(__half2 h) {
    return *reinterpret_cast<unsigned*>(&h);
}

// ---------------- kernel 1: pack Adj -> bitmask AND fp32->fp16 conversions ----------------
__global__ void prep_kernel(const int* __restrict__ Adj, const float* __restrict__ x,
                            const float* __restrict__ wq, const float* __restrict__ wv,
                            const float* __restrict__ wo) {
    int b = blockIdx.x;
    if (b < 65536) {
        int t = b * 256 + threadIdx.x;
        int n = t >> 12;
        int m = t & (NN - 1);
        unsigned bit = (Adj[(size_t)t] != 0) ? 1u : 0u;
        unsigned word = __ballot_sync(0xffffffffu, bit);
        if ((m & 31) == 0) g_mask[n][m >> 5] = word;
    } else {
        int i = (b - 65536) * 256 + threadIdx.x;   // half2 index
        if (i < 524288) {
            float2 f = ((const float2*)x)[i];
            ((__half2*)g_xh)[i] = __floats2half2_rn(f.x, f.y);
        } else if (i < 557056) {
            int j = i - 524288;
            float2 f = ((const float2*)wq)[j];
            ((__half2*)g_wqh)[j] = __floats2half2_rn(f.x, f.y);
        } else if (i < 589824) {
            int j = i - 557056;
            float2 f = ((const float2*)wv)[j];
            ((__half2*)g_wvh)[j] = __floats2half2_rn(f.x, f.y);
        } else {
            int j = i - 589824;
            float2 f = ((const float2*)wo)[j];
            ((__half2*)g_woh)[j] = __floats2half2_rn(f.x, f.y);
        }
    }
}

// ---------------- tensor-core projection GEMMs ----------------
__global__ __launch_bounds__(256, 2) void gemm16_qv_kernel(const float* __restrict__ bq,
                                                           const float* __restrict__ bv) {
    __shared__ __half xs[128 * 72];
    __shared__ __half ws[64 * 72];
    const int tid = threadIdx.x, warp = tid >> 5, lane = tid & 31;
    const int g = lane >> 2, tq = lane & 3;
    const int li = lane >> 3, lj = lane & 7;
    const int m0 = blockIdx.x * 128, o0 = blockIdx.y * 64;
    const __half* A = g_xh;
    const __half* B = blockIdx.z ? g_wvh : g_wqh;
    const float* bias = blockIdx.z ? bv : bq;
    __half* dst = blockIdx.z ? &g_v[0][0][0] : &g_q[0][0][0];

    const uint32_t xa = smem_u32(xs) + ((16 * warp + (li & 1) * 8 + lj) * 72 + (li >> 1) * 8) * 2;
    const uint32_t wb = smem_u32(ws) + (((li >> 1) * 8 + lj) * 72 + (li & 1) * 8) * 2;

    float acc[8][4];
#pragma unroll
    for (int s = 0; s < 8; s++)
#pragma unroll
        for (int j = 0; j < 4; j++) acc[s][j] = 0.f;

    for (int kb = 0; kb < HID; kb += 64) {
        __syncthreads();
#pragma unroll
        for (int i = 0; i < 4; i++) {
            int idx = tid + i * 256;
            int r = idx >> 3, c8 = (idx & 7) * 8;
            *(uint4*)&xs[r * 72 + c8] = *(const uint4*)&A[(size_t)(m0 + r) * HID + kb + c8];
        }
#pragma unroll
        for (int i = 0; i < 2; i++) {
            int idx = tid + i * 256;
            int r = idx >> 3, c8 = (idx & 7) * 8;
            *(uint4*)&ws[r * 72 + c8] = *(const uint4*)&B[(size_t)(o0 + r) * HID + kb + c8];
        }
        __syncthreads();
#pragma unroll
        for (int kc = 0; kc < 4; kc++) {
            unsigned a[4];
            LDSM_X4(a, xa + kc * 32);
#pragma unroll
            for (int subp = 0; subp < 4; subp++) {
                unsigned b[4];
                LDSM_X4(b, wb + subp * 2304 + kc * 32);
                mma_f16(acc[2 * subp], a[0], a[1], a[2], a[3], b[0], b[1]);
                mma_f16(acc[2 * subp + 1], a[0], a[1], a[2], a[3], b[2], b[3]);
            }
        }
    }
    const int r0 = m0 + 16 * warp + g, r1 = r0 + 8;
#pragma unroll
    for (int sub = 0; sub < 8; sub++) {
        int o = o0 + sub * 8 + 2 * tq;
        float b0 = bias[o], b1 = bias[o + 1];
        int hd = o >> 5, cc = o & 31;
        *(__half2*)&dst[((size_t)hd * NN + r0) * HEADD + cc] =
            __floats2half2_rn(acc[sub][0] + b0, acc[sub][1] + b1);
        *(__half2*)&dst[((size_t)hd * NN + r1) * HEADD + cc] =
            __floats2half2_rn(acc[sub][2] + b0, acc[sub][3] + b1);
    }
}

__global__ __launch_bounds__(256, 2) void gemm16_o_kernel(const float* __restrict__ bias,
                                                          float* __restrict__ Out) {
    __shared__ __half xs[128 * 72];
    __shared__ __half ws[64 * 72];
    const int tid = threadIdx.x, warp = tid >> 5, lane = tid & 31;
    const int g = lane >> 2, tq = lane & 3;
    const int li = lane >> 3, lj = lane & 7;
    const int m0 = blockIdx.x * 128, o0 = blockIdx.y * 64;
    const __half* A = g_obh;
    const __half* B = g_woh;

    const uint32_t xa = smem_u32(xs) + ((16 * warp + (li & 1) * 8 + lj) * 72 + (li >> 1) * 8) * 2;
    const uint32_t wb = smem_u32(ws) + (((li >> 1) * 8 + lj) * 72 + (li & 1) * 8) * 2;

    float acc[8][4];
#pragma unroll
    for (int s = 0; s < 8; s++)
#pragma unroll
        for (int j = 0; j < 4; j++) acc[s][j] = 0.f;

    for (int kb = 0; kb < HID; kb += 64) {
        __syncthreads();
#pragma unroll
        for (int i = 0; i < 4; i++) {
            int idx = tid + i * 256;
            int r = idx >> 3, c8 = (idx & 7) * 8;
            *(uint4*)&xs[r * 72 + c8] = *(const uint4*)&A[(size_t)(m0 + r) * HID + kb + c8];
        }
#pragma unroll
        for (int i = 0; i < 2; i++) {
            int idx = tid + i * 256;
            int r = idx >> 3, c8 = (idx & 7) * 8;
            *(uint4*)&ws[r * 72 + c8] = *(const uint4*)&B[(size_t)(o0 + r) * HID + kb + c8];
        }
        __syncthreads();
#pragma unroll
        for (int kc = 0; kc < 4; kc++) {
            unsigned a[4];
            LDSM_X4(a, xa + kc * 32);
#pragma unroll
            for (int subp = 0; subp < 4; subp++) {
                unsigned b[4];
                LDSM_X4(b, wb + subp * 2304 + kc * 32);
                mma_f16(acc[2 * subp], a[0], a[1], a[2], a[3], b[0], b[1]);
                mma_f16(acc[2 * subp + 1], a[0], a[1], a[2], a[3], b[2], b[3]);
            }
        }
    }
    const int r0 = m0 + 16 * warp + g, r1 = r0 + 8;
#pragma unroll
    for (int sub = 0; sub < 8; sub++) {
        int o = o0 + sub * 8 + 2 * tq;
        float b0 = bias[o], b1 = bias[o + 1];
        *(float2*)&Out[(size_t)r0 * HID + o] = make_float2(acc[sub][0] + b0, acc[sub][1] + b1);
        *(float2*)&Out[(size_t)r1 * HID + o] = make_float2(acc[sub][2] + b0, acc[sub][3] + b1);
    }
}

// ---------------- attention phase 1: rowsums + O (double-buffered) ----------------
constexpr int QS_OFF  = 0;        // [64][40] half   (5120 B)
constexpr int VS0_OFF = 5120;     // [128][40] half  (10240 B)
constexpr int VS1_OFF = 15360;    // [128][40] half  (10240 B)
constexpr int MS0_OFF = 25600;    // [64][4] unsigned (1024 B)
constexpr int MS1_OFF = 26624;    // [64][4] unsigned (1024 B)
constexpr int RS_OFF  = 27648;    // [2][64] float    (512 B)
constexpr int SMEM_P1 = 28160;

__global__ __launch_bounds__(256, 2) void attn_phase1_kernel() {
    extern __shared__ char sm[];
    __half* qs  = (__half*)(sm + QS_OFF);
    __half* vs0 = (__half*)(sm + VS0_OFF);
    __half* vs1 = (__half*)(sm + VS1_OFF);
    unsigned* ms0 = (unsigned*)(sm + MS0_OFF);
    unsigned* ms1 = (unsigned*)(sm + MS1_OFF);
    float* rsA = (float*)(sm + RS_OFF);
    const uint32_t sb = smem_u32(sm);

    const int head = blockIdx.y;
    const int n0 = blockIdx.x * 64;
    const int tid = threadIdx.x;
    const int wid = tid >> 5, lane = tid & 31;
    const int rw = wid & 3, cw = wid >> 2;
    const int g = lane >> 2, tq = lane & 3;
    const int li = lane >> 3, lj = lane & 7;
    const int r0 = rw * 16 + g;
    const int r1 = r0 + 8;

    const uint32_t qa_base = sb + QS_OFF + ((rw * 16 + (li & 1) * 8 + lj) * 40 + (li >> 1) * 8) * 2;
    const uint32_t vb0 = sb + VS0_OFF + ((cw * 64 + (li >> 1) * 8 + lj) * 40 + (li & 1) * 8) * 2;
    const uint32_t vt0 = sb + VS0_OFF + ((cw * 64 + (li & 1) * 8 + lj) * 40 + (li >> 1) * 8) * 2;

    const __half* vhead = &g_v[head][0][0];
    const int pr = tid >> 2, pc8 = (tid & 3) * 8;

    *(uint4*)&qs[pr * 40 + pc8] = *(const uint4*)&g_q[head][n0 + pr][pc8];
#pragma unroll
    for (int i = 0; i < 2; i++)
        *(uint4*)&vs0[(pr + i * 64) * 40 + pc8] = *(const uint4*)&vhead[(pr + i * 64) * 32 + pc8];
    ms0[tid] = g_mask[n0 + (tid >> 2)][tid & 3];
    __syncthreads();

    float oacc[4][4];
#pragma unroll
    for (int i = 0; i < 4; i++)
#pragma unroll
        for (int j = 0; j < 4; j++) oacc[i][j] = 0.f;
    float rs0 = 0.f, rs1 = 0.f;

    for (int tile = 0; tile < 32; tile++) {
        const uint32_t voff = (tile & 1) ? 10240u : 0u;
        unsigned* msp = (tile & 1) ? ms1 : ms0;

        uint4 pv0, pv1;
        unsigned pm = 0;
        if (tile < 31) {
            const __half* vsrc = &vhead[(tile + 1) * 128 * 32];
            pv0 = *(const uint4*)&vsrc[pr * 32 + pc8];
            pv1 = *(const uint4*)&vsrc[(pr + 64) * 32 + pc8];
            pm = g_mask[n0 + (tid >> 2)][(tile + 1) * 4 + (tid & 3)];
        }

        float c[8][4];
#pragma unroll
        for (int s = 0; s < 8; s++)
#pragma unroll
            for (int j = 0; j < 4; j++) c[s][j] = 0.f;
#pragma unroll
        for (int kc = 0; kc < 2; kc++) {
            unsigned a[4];
            LDSM_X4(a, qa_base + kc * 32);
#pragma unroll
            for (int subp = 0; subp < 4; subp++) {
                unsigned b[4];
                LDSM_X4(b, vb0 + voff + subp * 1280 + kc * 32);
                mma_f16(c[2 * subp], a[0], a[1], a[2], a[3], b[0], b[1]);
                mma_f16(c[2 * subp + 1], a[0], a[1], a[2], a[3], b[2], b[3]);
            }
        }

        unsigned ah0[8], ah1[8];
#pragma unroll
        for (int sub = 0; sub < 8; sub++) {
            int cword = cw * 2 + (sub >> 2);
            unsigned w0 = msp[r0 * 4 + cword];
            unsigned w1 = msp[r1 * 4 + cword];
            int sh = (sub * 8 + 2 * tq) & 31;
            float e0 = ((w0 >> sh) & 1u) ? ex2f(c[sub][0] * EXS) : 0.f;
            float e1 = ((w0 >> sh) & 2u) ? ex2f(c[sub][1] * EXS) : 0.f;
            float e2 = ((w1 >> sh) & 1u) ? ex2f(c[sub][2] * EXS) : 0.f;
            float e3 = ((w1 >> sh) & 2u) ? ex2f(c[sub][3] * EXS) : 0.f;
            rs0 += e0 + e1;
            rs1 += e2 + e3;
            ah0[sub] = h2u(__floats2half2_rn(e0, e1));
            ah1[sub] = h2u(__floats2half2_rn(e2, e3));
        }

#pragma unroll
        for (int kc2 = 0; kc2 < 4; kc2++) {
            unsigned a0 = ah0[2 * kc2], a1 = ah1[2 * kc2];
            unsigned a2 = ah0[2 * kc2 + 1], a3 = ah1[2 * kc2 + 1];
#pragma unroll
            for (int dsp = 0; dsp < 2; dsp++) {
                unsigned t[4];
                LDSM_X4T(t, vt0 + voff + kc2 * 1280 + dsp * 32);
                mma_f16(oacc[2 * dsp], a0, a1, a2, a3, t[0], t[1]);
                mma_f16(oacc[2 * dsp + 1], a0, a1, a2, a3, t[2], t[3]);
            }
        }

        if (tile < 31) {
            __half* vd = (tile & 1) ? vs0 : vs1;
            unsigned* md = (tile & 1) ? ms0 : ms1;
            *(uint4*)&vd[pr * 40 + pc8] = pv0;
            *(uint4*)&vd[(pr + 64) * 40 + pc8] = pv1;
            md[tid] = pm;
        }
        __syncthreads();
    }

    rs0 += __shfl_xor_sync(0xffffffffu, rs0, 1);
    rs0 += __shfl_xor_sync(0xffffffffu, rs0, 2);
    rs1 += __shfl_xor_sync(0xffffffffu, rs1, 1);
    rs1 += __shfl_xor_sync(0xffffffffu, rs1, 2);
    if (tq == 0) {
        rsA[cw * 64 + r0] = rs0;
        rsA[cw * 64 + r1] = rs1;
    }
    __syncthreads();
    if (tid < 64)
        g_inv[head][n0 + tid] = 1.0f / (rsA[tid] + rsA[64 + tid]);
    const float inv0 = 1.0f / (rsA[r0] + rsA[64 + r0]);
    const float inv1 = 1.0f / (rsA[r1] + rsA[64 + r1]);

    float* obr = (float*)(sm + VS0_OFF);
    if (cw == 0) {
#pragma unroll
        for (int ds = 0; ds < 4; ds++) {
            int col = ds * 8 + 2 * tq;
            *(float2*)&obr[r0 * 32 + col] = make_float2(oacc[ds][0], oacc[ds][1]);
            *(float2*)&obr[r1 * 32 + col] = make_float2(oacc[ds][2], oacc[ds][3]);
        }
    }
    __syncthreads();
    if (cw == 1) {
#pragma unroll
        for (int ds = 0; ds < 4; ds++) {
            int col = ds * 8 + 2 * tq;
            float2 p0 = *(const float2*)&obr[r0 * 32 + col];
            float2 p1 = *(const float2*)&obr[r1 * 32 + col];
            *(__half2*)&g_obh[(size_t)(n0 + r0) * HID + head * 32 + col] =
                __floats2half2_rn((oacc[ds][0] + p0.x) * inv0, (oacc[ds][1] + p0.y) * inv0);
            *(__half2*)&g_obh[(size_t)(n0 + r1) * HID + head * 32 + col] =
                __floats2half2_rn((oacc[ds][2] + p1.x) * inv1, (oacc[ds][3] + p1.y) * inv1);
        }
    }
}

// ---------------- attention phase 2: recompute S, normalize, smem-staged coalesced store ----------------
constexpr int P2_QS  = 0;         // [64][40] half   (5120 B)
constexpr int P2_VS0 = 5120;      // [128][40] half  (10240 B)
constexpr int P2_VS1 = 15360;     // [128][40] half  (10240 B)
constexpr int P2_MS0 = 25600;     // [64][4] unsigned (1024 B)
constexpr int P2_MS1 = 26624;     // [64][4] unsigned (1024 B)
constexpr int P2_ES  = 27648;     // [64][132] float  (33792 B)
constexpr int SMEM_P2 = 61440;

__global__ __launch_bounds__(256, 3) void attn_phase2_kernel(float* __restrict__ attn_out) {
    extern __shared__ char sm[];
    __half* qs  = (__half*)(sm + P2_QS);
    __half* vs0 = (__half*)(sm + P2_VS0);
    __half* vs1 = (__half*)(sm + P2_VS1);
    unsigned* ms0 = (unsigned*)(sm + P2_MS0);
    unsigned* ms1 = (unsigned*)(sm + P2_MS1);
    float* es = (float*)(sm + P2_ES);           // row stride 132 floats
    const uint32_t sb = smem_u32(sm);

    const int head = blockIdx.y;
    const int n0 = blockIdx.x * 64;
    const int tid = threadIdx.x;
    const int wid = tid >> 5, lane = tid & 31;
    const int rw = wid & 3, cw = wid >> 2;
    const int g = lane >> 2, tq = lane & 3;
    const int li = lane >> 3, lj = lane & 7;
    const int r0 = rw * 16 + g;
    const int r1 = r0 + 8;

    const uint32_t qa_base = sb + P2_QS + ((rw * 16 + (li & 1) * 8 + lj) * 40 + (li >> 1) * 8) * 2;
    const uint32_t vb0 = sb + P2_VS0 + ((cw * 64 + (li >> 1) * 8 + lj) * 40 + (li & 1) * 8) * 2;

    const __half* vhead = &g_v[head][0][0];
    const int pr = tid >> 2, pc8 = (tid & 3) * 8;

    *(uint4*)&qs[pr * 40 + pc8] = *(const uint4*)&g_q[head][n0 + pr][pc8];
#pragma unroll
    for (int i = 0; i < 2; i++)
        *(uint4*)&vs0[(pr + i * 64) * 40 + pc8] = *(const uint4*)&vhead[(pr + i * 64) * 32 + pc8];
    ms0[tid] = g_mask[n0 + (tid >> 2)][tid & 3];

    // normalization folded into exponent: e = ex2(c*EXS + log2(inv))
    const float lg0 = __log2f(g_inv[head][n0 + r0]);
    const float lg1 = __log2f(g_inv[head][n0 + r1]);
    __syncthreads();

    // coalesced copy-out lane coords: 64 rows x 32 float4-chunks per tile
    const int orow = tid >> 5;          // rows handled: orow, orow+8, ... (8 iters)
    const int och = (tid & 31) * 4;     // float index within tile row
    float* obase = &attn_out[((size_t)(head * NN + n0)) * NN];

    for (int tile = 0; tile < 32; tile++) {
        const uint32_t voff = (tile & 1) ? 10240u : 0u;
        unsigned* msp = (tile & 1) ? ms1 : ms0;

        uint4 pv0, pv1;
        unsigned pm = 0;
        if (tile < 31) {
            const __half* vsrc = &vhead[(tile + 1) * 128 * 32];
            pv0 = *(const uint4*)&vsrc[pr * 32 + pc8];
            pv1 = *(const uint4*)&vsrc[(pr + 64) * 32 + pc8];
            pm = g_mask[n0 + (tid >> 2)][(tile + 1) * 4 + (tid & 3)];
        }

        float c[8][4];
#pragma unroll
        for (int s = 0; s < 8; s++)
#pragma unroll
            for (int j = 0; j < 4; j++) c[s][j] = 0.f;
#pragma unroll
        for (int kc = 0; kc < 2; kc++) {
            unsigned a[4];
            LDSM_X4(a, qa_base + kc * 32);
#pragma unroll
            for (int subp = 0; subp < 4; subp++) {
                unsigned b[4];
                LDSM_X4(b, vb0 + voff + subp * 1280 + kc * 32);
                mma_f16(c[2 * subp], a[0], a[1], a[2], a[3], b[0], b[1]);
                mma_f16(c[2 * subp + 1], a[0], a[1], a[2], a[3], b[2], b[3]);
            }
        }

        // mask + ex2(normalized) -> stage into es (fragment-shaped smem writes)
#pragma unroll
        for (int sub = 0; sub < 8; sub++) {
            int cword = cw * 2 + (sub >> 2);
            unsigned w0 = msp[r0 * 4 + cword];
            unsigned w1 = msp[r1 * 4 + cword];
            int col = cw * 64 + sub * 8 + 2 * tq;
            int sh = (sub * 8 + 2 * tq) & 31;
            float e0 = ((w0 >> sh) & 1u) ? ex2f(fmaf(c[sub][0], EXS, lg0)) : 0.f;
            float e1 = ((w0 >> sh) & 2u) ? ex2f(fmaf(c[sub][1], EXS, lg0)) : 0.f;
            float e2 = ((w1 >> sh) & 1u) ? ex2f(fmaf(c[sub][2], EXS, lg1)) : 0.f;
            float e3 = ((w1 >> sh) & 2u) ? ex2f(fmaf(c[sub][3], EXS, lg1)) : 0.f;
            *(float2*)&es[r0 * 132 + col] = make_float2(e0, e1);
            *(float2*)&es[r1 * 132 + col] = make_float2(e2, e3);
        }

        // stage next V tile
        if (tile < 31) {
            __half* vd = (tile & 1) ? vs0 : vs1;
            unsigned* md = (tile & 1) ? ms0 : ms1;
            *(uint4*)&vd[pr * 40 + pc8] = pv0;
            *(uint4*)&vd[(pr + 64) * 40 + pc8] = pv1;
            md[tid] = pm;
        }
        __syncthreads();   // es complete + next V staged

        // coalesced copy-out: 64x128 tile, warp writes 512B consecutive per instr
        {
            float* dst = obase + tile * 128;
#pragma unroll
            for (int i = 0; i < 8; i++) {
                int r = orow + i * 8;
                float4 v = *(const float4*)&es[r * 132 + och];
                __stcs((float4*)&dst[(size_t)r * NN + och], v);
            }
        }
        __syncthreads();   // es drained before next tile overwrites
    }
}

// ---------------- launch ----------------
extern "C" void kernel_launch(void* const* d_in, const int* in_sizes, int n_in,
                              void* d_out, int out_size) {
    (void)in_sizes; (void)n_in; (void)out_size;
    const float* x   = (const float*)d_in[0];
    const int*   Adj = (const int*)d_in[1];
    const float* wq  = (const float*)d_in[2];
    const float* bq  = (const float*)d_in[3];
    // wk (d_in[4], d_in[5]) unused: reference has the q@v^T bug
    const float* wv  = (const float*)d_in[6];
    const float* bv  = (const float*)d_in[7];
    const float* wo  = (const float*)d_in[8];
    const float* bo  = (const float*)d_in[9];
    float* out  = (float*)d_out;
    float* attn = out + (size_t)NN * HID;

    cudaFuncSetAttribute(attn_phase1_kernel,
                         cudaFuncAttributeMaxDynamicSharedMemorySize, SMEM_P1);
    cudaFuncSetAttribute(attn_phase2_kernel,
                         cudaFuncAttributeMaxDynamicSharedMemorySize, SMEM_P2);

    prep_kernel<<<65536 + 2432, 256>>>(Adj, x, wq, wv, wo);          // #1
    gemm16_qv_kernel<<<dim3(32, 4, 2), 256>>>(bq, bv);               // #2
    attn_phase1_kernel<<<dim3(64, 8), 256, SMEM_P1>>>();             // #3
    attn_phase2_kernel<<<dim3(64, 8), 256, SMEM_P2>>>(attn);         // #4 <- profiled
    gemm16_o_kernel<<<dim3(32, 4), 256>>>(bo, out);                  // #5
}

// round 14
// speedup vs baseline: 1.1372x; 1.1372x over previous
#include <cuda_runtime.h>
#include <cuda_fp16.h>
#include <cstdint>

#define NN 4096
#define HID 256
#define NHEADS 8
#define HEADD 32
#define EXS 0.2550390270190456f   // (1/sqrt(32)) * log2(e)

// ---------------- scratch (static device globals; no allocation) ----------------
__device__ __half   g_q[NHEADS][NN][HEADD];     // fp16 q, head-major
__device__ __half   g_v[NHEADS][NN][HEADD];     // fp16 v, head-major
__device__ __half   g_xh[NN * HID];             // fp16 x
__device__ __half   g_wqh[HID * HID];
__device__ __half   g_wvh[HID * HID];
__device__ __half   g_woh[HID * HID];
__device__ __half   g_obh[NN * HID];            // fp16 normalized attn@v
__device__ float    g_inv[NHEADS][NN];          // 1/rowsum
__device__ unsigned g_mask[NN][NN / 32];        // Adj packed to bits

// ---------------- helpers ----------------
__device__ __forceinline__ uint32_t smem_u32(const void* p) {
    uint32_t a;
    asm("{ .reg .u64 t; cvta.to.shared.u64 t, %1; cvt.u32.u64 %0, t; }" : "=r"(a) : "l"(p));
    return a;
}
__device__ __forceinline__ float ex2f(float x) {
    float y;
    asm("ex2.approx.f32 %0, %1;" : "=f"(y) : "f"(x));
    return y;
}
__device__ __forceinline__ void mma_f16(float c[4],
                                        unsigned a0, unsigned a1, unsigned a2, unsigned a3,
                                        unsigned b0, unsigned b1) {
    asm volatile(
        "mma.sync.aligned.m16n8k16.row.col.f32.f16.f16.f32 "
        "{%0,%1,%2,%3},{%4,%5,%6,%7},{%8,%9},{%0,%1,%2,%3};\n"
        : "+f"(c[0]), "+f"(c[1]), "+f"(c[2]), "+f"(c[3])
        : "r"(a0), "r"(a1), "r"(a2), "r"(a3), "r"(b0), "r"(b1));
}
#define LDSM_X4(d, addr) \
    asm volatile("ldmatrix.sync.aligned.m8n8.x4.shared.b16 {%0,%1,%2,%3}, [%4];" \
        : "=r"((d)[0]), "=r"((d)[1]), "=r"((d)[2]), "=r"((d)[3]) : "r"(addr))
#define LDSM_X4T(d, addr) \
    asm volatile("ldmatrix.sync.aligned.m8n8.x4.trans.shared.b16 {%0,%1,%2,%3}, [%4];" \
        : "=r"((d)[0]), "=r"((d)[1]), "=r"((d)[2]), "=r"((d)[3]) : "r"(addr))
__device__ __forceinline__ unsigned h2u(__half2 h) {
    return *reinterpret_cast<unsigned*>(&h);
}

// ---------------- kernel 1: pack Adj -> bitmask AND fp32->fp16 conversions ----------------
__global__ void prep_kernel(const int* __restrict__ Adj, const float* __restrict__ x,
                            const float* __restrict__ wq, const float* __restrict__ wv,
                            const float* __restrict__ wo) {
    int b = blockIdx.x;
    if (b < 65536) {
        int t = b * 256 + threadIdx.x;
        int n = t >> 12;
        int m = t & (NN - 1);
        unsigned bit = (Adj[(size_t)t] != 0) ? 1u : 0u;
        unsigned word = __ballot_sync(0xffffffffu, bit);
        if ((m & 31) == 0) g_mask[n][m >> 5] = word;
    } else {
        int i = (b - 65536) * 256 + threadIdx.x;   // half2 index
        if (i < 524288) {
            float2 f = ((const float2*)x)[i];
            ((__half2*)g_xh)[i] = __floats2half2_rn(f.x, f.y);
        } else if (i < 557056) {
            int j = i - 524288;
            float2 f = ((const float2*)wq)[j];
            ((__half2*)g_wqh)[j] = __floats2half2_rn(f.x, f.y);
        } else if (i < 589824) {
            int j = i - 557056;
            float2 f = ((const float2*)wv)[j];
            ((__half2*)g_wvh)[j] = __floats2half2_rn(f.x, f.y);
        } else {
            int j = i - 589824;
            float2 f = ((const float2*)wo)[j];
            ((__half2*)g_woh)[j] = __floats2half2_rn(f.x, f.y);
        }
    }
}

// ---------------- tensor-core projection GEMMs ----------------
__global__ __launch_bounds__(256, 2) void gemm16_qv_kernel(const float* __restrict__ bq,
                                                           const float* __restrict__ bv) {
    __shared__ __half xs[128 * 72];
    __shared__ __half ws[64 * 72];
    const int tid = threadIdx.x, warp = tid >> 5, lane = tid & 31;
    const int g = lane >> 2, tq = lane & 3;
    const int li = lane >> 3, lj = lane & 7;
    const int m0 = blockIdx.x * 128, o0 = blockIdx.y * 64;
    const __half* A = g_xh;
    const __half* B = blockIdx.z ? g_wvh : g_wqh;
    const float* bias = blockIdx.z ? bv : bq;
    __half* dst = blockIdx.z ? &g_v[0][0][0] : &g_q[0][0][0];

    const uint32_t xa = smem_u32(xs) + ((16 * warp + (li & 1) * 8 + lj) * 72 + (li >> 1) * 8) * 2;
    const uint32_t wb = smem_u32(ws) + (((li >> 1) * 8 + lj) * 72 + (li & 1) * 8) * 2;

    float acc[8][4];
#pragma unroll
    for (int s = 0; s < 8; s++)
#pragma unroll
        for (int j = 0; j < 4; j++) acc[s][j] = 0.f;

    for (int kb = 0; kb < HID; kb += 64) {
        __syncthreads();
#pragma unroll
        for (int i = 0; i < 4; i++) {
            int idx = tid + i * 256;
            int r = idx >> 3, c8 = (idx & 7) * 8;
            *(uint4*)&xs[r * 72 + c8] = *(const uint4*)&A[(size_t)(m0 + r) * HID + kb + c8];
        }
#pragma unroll
        for (int i = 0; i < 2; i++) {
            int idx = tid + i * 256;
            int r = idx >> 3, c8 = (idx & 7) * 8;
            *(uint4*)&ws[r * 72 + c8] = *(const uint4*)&B[(size_t)(o0 + r) * HID + kb + c8];
        }
        __syncthreads();
#pragma unroll
        for (int kc = 0; kc < 4; kc++) {
            unsigned a[4];
            LDSM_X4(a, xa + kc * 32);
#pragma unroll
            for (int subp = 0; subp < 4; subp++) {
                unsigned b[4];
                LDSM_X4(b, wb + subp * 2304 + kc * 32);
                mma_f16(acc[2 * subp], a[0], a[1], a[2], a[3], b[0], b[1]);
                mma_f16(acc[2 * subp + 1], a[0], a[1], a[2], a[3], b[2], b[3]);
            }
        }
    }
    const int r0 = m0 + 16 * warp + g, r1 = r0 + 8;
#pragma unroll
    for (int sub = 0; sub < 8; sub++) {
        int o = o0 + sub * 8 + 2 * tq;
        float b0 = bias[o], b1 = bias[o + 1];
        int hd = o >> 5, cc = o & 31;
        *(__half2*)&dst[((size_t)hd * NN + r0) * HEADD + cc] =
            __floats2half2_rn(acc[sub][0] + b0, acc[sub][1] + b1);
        *(__half2*)&dst[((size_t)hd * NN + r1) * HEADD + cc] =
            __floats2half2_rn(acc[sub][2] + b0, acc[sub][3] + b1);
    }
}

__global__ __launch_bounds__(256, 2) void gemm16_o_kernel(const float* __restrict__ bias,
                                                          float* __restrict__ Out) {
    __shared__ __half xs[128 * 72];
    __shared__ __half ws[64 * 72];
    const int tid = threadIdx.x, warp = tid >> 5, lane = tid & 31;
    const int g = lane >> 2, tq = lane & 3;
    const int li = lane >> 3, lj = lane & 7;
    const int m0 = blockIdx.x * 128, o0 = blockIdx.y * 64;
    const __half* A = g_obh;
    const __half* B = g_woh;

    const uint32_t xa = smem_u32(xs) + ((16 * warp + (li & 1) * 8 + lj) * 72 + (li >> 1) * 8) * 2;
    const uint32_t wb = smem_u32(ws) + (((li >> 1) * 8 + lj) * 72 + (li & 1) * 8) * 2;

    float acc[8][4];
#pragma unroll
    for (int s = 0; s < 8; s++)
#pragma unroll
        for (int j = 0; j < 4; j++) acc[s][j] = 0.f;

    for (int kb = 0; kb < HID; kb += 64) {
        __syncthreads();
#pragma unroll
        for (int i = 0; i < 4; i++) {
            int idx = tid + i * 256;
            int r = idx >> 3, c8 = (idx & 7) * 8;
            *(uint4*)&xs[r * 72 + c8] = *(const uint4*)&A[(size_t)(m0 + r) * HID + kb + c8];
        }
#pragma unroll
        for (int i = 0; i < 2; i++) {
            int idx = tid + i * 256;
            int r = idx >> 3, c8 = (idx & 7) * 8;
            *(uint4*)&ws[r * 72 + c8] = *(const uint4*)&B[(size_t)(o0 + r) * HID + kb + c8];
        }
        __syncthreads();
#pragma unroll
        for (int kc = 0; kc < 4; kc++) {
            unsigned a[4];
            LDSM_X4(a, xa + kc * 32);
#pragma unroll
            for (int subp = 0; subp < 4; subp++) {
                unsigned b[4];
                LDSM_X4(b, wb + subp * 2304 + kc * 32);
                mma_f16(acc[2 * subp], a[0], a[1], a[2], a[3], b[0], b[1]);
                mma_f16(acc[2 * subp + 1], a[0], a[1], a[2], a[3], b[2], b[3]);
            }
        }
    }
    const int r0 = m0 + 16 * warp + g, r1 = r0 + 8;
#pragma unroll
    for (int sub = 0; sub < 8; sub++) {
        int o = o0 + sub * 8 + 2 * tq;
        float b0 = bias[o], b1 = bias[o + 1];
        *(float2*)&Out[(size_t)r0 * HID + o] = make_float2(acc[sub][0] + b0, acc[sub][1] + b1);
        *(float2*)&Out[(size_t)r1 * HID + o] = make_float2(acc[sub][2] + b0, acc[sub][3] + b1);
    }
}

// ---------------- attention phase 1: rowsums + O (double-buffered) ----------------
constexpr int QS_OFF  = 0;        // [64][40] half   (5120 B)
constexpr int VS0_OFF = 5120;     // [128][40] half  (10240 B)
constexpr int VS1_OFF = 15360;    // [128][40] half  (10240 B)
constexpr int MS0_OFF = 25600;    // [64][4] unsigned (1024 B)
constexpr int MS1_OFF = 26624;    // [64][4] unsigned (1024 B)
constexpr int RS_OFF  = 27648;    // [2][64] float    (512 B)
constexpr int SMEM_P1 = 28160;

__global__ __launch_bounds__(256, 2) void attn_phase1_kernel() {
    extern __shared__ char sm[];
    __half* qs  = (__half*)(sm + QS_OFF);
    __half* vs0 = (__half*)(sm + VS0_OFF);
    __half* vs1 = (__half*)(sm + VS1_OFF);
    unsigned* ms0 = (unsigned*)(sm + MS0_OFF);
    unsigned* ms1 = (unsigned*)(sm + MS1_OFF);
    float* rsA = (float*)(sm + RS_OFF);
    const uint32_t sb = smem_u32(sm);

    const int head = blockIdx.y;
    const int n0 = blockIdx.x * 64;
    const int tid = threadIdx.x;
    const int wid = tid >> 5, lane = tid & 31;
    const int rw = wid & 3, cw = wid >> 2;
    const int g = lane >> 2, tq = lane & 3;
    const int li = lane >> 3, lj = lane & 7;
    const int r0 = rw * 16 + g;
    const int r1 = r0 + 8;

    const uint32_t qa_base = sb + QS_OFF + ((rw * 16 + (li & 1) * 8 + lj) * 40 + (li >> 1) * 8) * 2;
    const uint32_t vb0 = sb + VS0_OFF + ((cw * 64 + (li >> 1) * 8 + lj) * 40 + (li & 1) * 8) * 2;
    const uint32_t vt0 = sb + VS0_OFF + ((cw * 64 + (li & 1) * 8 + lj) * 40 + (li >> 1) * 8) * 2;

    const __half* vhead = &g_v[head][0][0];
    const int pr = tid >> 2, pc8 = (tid & 3) * 8;

    *(uint4*)&qs[pr * 40 + pc8] = *(const uint4*)&g_q[head][n0 + pr][pc8];
#pragma unroll
    for (int i = 0; i < 2; i++)
        *(uint4*)&vs0[(pr + i * 64) * 40 + pc8] = *(const uint4*)&vhead[(pr + i * 64) * 32 + pc8];
    ms0[tid] = g_mask[n0 + (tid >> 2)][tid & 3];
    __syncthreads();

    float oacc[4][4];
#pragma unroll
    for (int i = 0; i < 4; i++)
#pragma unroll
        for (int j = 0; j < 4; j++) oacc[i][j] = 0.f;
    float rs0 = 0.f, rs1 = 0.f;

    for (int tile = 0; tile < 32; tile++) {
        const uint32_t voff = (tile & 1) ? 10240u : 0u;
        unsigned* msp = (tile & 1) ? ms1 : ms0;

        uint4 pv0, pv1;
        unsigned pm = 0;
        if (tile < 31) {
            const __half* vsrc = &vhead[(tile + 1) * 128 * 32];
            pv0 = *(const uint4*)&vsrc[pr * 32 + pc8];
            pv1 = *(const uint4*)&vsrc[(pr + 64) * 32 + pc8];
            pm = g_mask[n0 + (tid >> 2)][(tile + 1) * 4 + (tid & 3)];
        }

        float c[8][4];
#pragma unroll
        for (int s = 0; s < 8; s++)
#pragma unroll
            for (int j = 0; j < 4; j++) c[s][j] = 0.f;
#pragma unroll
        for (int kc = 0; kc < 2; kc++) {
            unsigned a[4];
            LDSM_X4(a, qa_base + kc * 32);
#pragma unroll
            for (int subp = 0; subp < 4; subp++) {
                unsigned b[4];
                LDSM_X4(b, vb0 + voff + subp * 1280 + kc * 32);
                mma_f16(c[2 * subp], a[0], a[1], a[2], a[3], b[0], b[1]);
                mma_f16(c[2 * subp + 1], a[0], a[1], a[2], a[3], b[2], b[3]);
            }
        }

        unsigned ah0[8], ah1[8];
#pragma unroll
        for (int sub = 0; sub < 8; sub++) {
            int cword = cw * 2 + (sub >> 2);
            unsigned w0 = msp[r0 * 4 + cword];
            unsigned w1 = msp[r1 * 4 + cword];
            int sh = (sub * 8 + 2 * tq) & 31;
            float e0 = ((w0 >> sh) & 1u) ? ex2f(c[sub][0] * EXS) : 0.f;
            float e1 = ((w0 >> sh) & 2u) ? ex2f(c[sub][1] * EXS) : 0.f;
            float e2 = ((w1 >> sh) & 1u) ? ex2f(c[sub][2] * EXS) : 0.f;
            float e3 = ((w1 >> sh) & 2u) ? ex2f(c[sub][3] * EXS) : 0.f;
            rs0 += e0 + e1;
            rs1 += e2 + e3;
            ah0[sub] = h2u(__floats2half2_rn(e0, e1));
            ah1[sub] = h2u(__floats2half2_rn(e2, e3));
        }

#pragma unroll
        for (int kc2 = 0; kc2 < 4; kc2++) {
            unsigned a0 = ah0[2 * kc2], a1 = ah1[2 * kc2];
            unsigned a2 = ah0[2 * kc2 + 1], a3 = ah1[2 * kc2 + 1];
#pragma unroll
            for (int dsp = 0; dsp < 2; dsp++) {
                unsigned t[4];
                LDSM_X4T(t, vt0 + voff + kc2 * 1280 + dsp * 32);
                mma_f16(oacc[2 * dsp], a0, a1, a2, a3, t[0], t[1]);
                mma_f16(oacc[2 * dsp + 1], a0, a1, a2, a3, t[2], t[3]);
            }
        }

        if (tile < 31) {
            __half* vd = (tile & 1) ? vs0 : vs1;
            unsigned* md = (tile & 1) ? ms0 : ms1;
            *(uint4*)&vd[pr * 40 + pc8] = pv0;
            *(uint4*)&vd[(pr + 64) * 40 + pc8] = pv1;
            md[tid] = pm;
        }
        __syncthreads();
    }

    rs0 += __shfl_xor_sync(0xffffffffu, rs0, 1);
    rs0 += __shfl_xor_sync(0xffffffffu, rs0, 2);
    rs1 += __shfl_xor_sync(0xffffffffu, rs1, 1);
    rs1 += __shfl_xor_sync(0xffffffffu, rs1, 2);
    if (tq == 0) {
        rsA[cw * 64 + r0] = rs0;
        rsA[cw * 64 + r1] = rs1;
    }
    __syncthreads();
    if (tid < 64)
        g_inv[head][n0 + tid] = 1.0f / (rsA[tid] + rsA[64 + tid]);
    const float inv0 = 1.0f / (rsA[r0] + rsA[64 + r0]);
    const float inv1 = 1.0f / (rsA[r1] + rsA[64 + r1]);

    float* obr = (float*)(sm + VS0_OFF);
    if (cw == 0) {
#pragma unroll
        for (int ds = 0; ds < 4; ds++) {
            int col = ds * 8 + 2 * tq;
            *(float2*)&obr[r0 * 32 + col] = make_float2(oacc[ds][0], oacc[ds][1]);
            *(float2*)&obr[r1 * 32 + col] = make_float2(oacc[ds][2], oacc[ds][3]);
        }
    }
    __syncthreads();
    if (cw == 1) {
#pragma unroll
        for (int ds = 0; ds < 4; ds++) {
            int col = ds * 8 + 2 * tq;
            float2 p0 = *(const float2*)&obr[r0 * 32 + col];
            float2 p1 = *(const float2*)&obr[r1 * 32 + col];
            *(__half2*)&g_obh[(size_t)(n0 + r0) * HID + head * 32 + col] =
                __floats2half2_rn((oacc[ds][0] + p0.x) * inv0, (oacc[ds][1] + p0.y) * inv0);
            *(__half2*)&g_obh[(size_t)(n0 + r1) * HID + head * 32 + col] =
                __floats2half2_rn((oacc[ds][2] + p1.x) * inv1, (oacc[ds][3] + p1.y) * inv1);
        }
    }
}

// ---------------- attention phase 2: M=32 CTAs, 4 CTAs/SM, recompute + stream attn ----------------
constexpr int P2_QS  = 0;         // [32][40] half   (2560 B)
constexpr int P2_VS0 = 2560;      // [128][40] half  (10240 B)
constexpr int P2_VS1 = 12800;     // [128][40] half  (10240 B)
constexpr int P2_MS0 = 23040;     // [32][4] unsigned (512 B)
constexpr int P2_MS1 = 23552;     // [32][4] unsigned (512 B)
constexpr int SMEM_P2 = 24576;

__global__ __launch_bounds__(256, 4) void attn_phase2_kernel(float* __restrict__ attn_out) {
    extern __shared__ char sm[];
    __half* qs  = (__half*)(sm + P2_QS);
    __half* vs0 = (__half*)(sm + P2_VS0);
    __half* vs1 = (__half*)(sm + P2_VS1);
    unsigned* ms0 = (unsigned*)(sm + P2_MS0);
    unsigned* ms1 = (unsigned*)(sm + P2_MS1);
    const uint32_t sb = smem_u32(sm);

    const int head = blockIdx.y;
    const int n0 = blockIdx.x * 32;
    const int tid = threadIdx.x;
    const int wid = tid >> 5, lane = tid & 31;
    const int rw = wid & 1, cw = wid >> 1;        // 2 row-groups x 4 col-groups(32)
    const int g = lane >> 2, tq = lane & 3;
    const int li = lane >> 3, lj = lane & 7;
    const int r0 = rw * 16 + g;                   // local rows 0..31
    const int r1 = r0 + 8;

    const uint32_t qa_base = sb + P2_QS + ((rw * 16 + (li & 1) * 8 + lj) * 40 + (li >> 1) * 8) * 2;
    const uint32_t vb0 = sb + P2_VS0 + ((cw * 32 + (li >> 1) * 8 + lj) * 40 + (li & 1) * 8) * 2;

    const __half* vhead = &g_v[head][0][0];
    const int pr = tid >> 2, pc8 = (tid & 3) * 8;

    if (tid < 128) {
        int r = tid >> 2, c8 = (tid & 3) * 8;
        *(uint4*)&qs[r * 40 + c8] = *(const uint4*)&g_q[head][n0 + r][c8];
        ms0[tid] = g_mask[n0 + (tid >> 2)][tid & 3];
    }
#pragma unroll
    for (int i = 0; i < 2; i++)
        *(uint4*)&vs0[(pr + i * 64) * 40 + pc8] = *(const uint4*)&vhead[(pr + i * 64) * 32 + pc8];

    // normalization folded into exponent: e = ex2(c*EXS + log2(inv))
    const float lg0 = __log2f(g_inv[head][n0 + r0]);
    const float lg1 = __log2f(g_inv[head][n0 + r1]);
    __syncthreads();

    float* a0row = &attn_out[((size_t)(head * NN + n0 + r0)) * NN + cw * 32 + 2 * tq];
    float* a1row = &attn_out[((size_t)(head * NN + n0 + r1)) * NN + cw * 32 + 2 * tq];

    for (int tile = 0; tile < 32; tile++) {
        const uint32_t voff = (tile & 1) ? 10240u : 0u;
        unsigned* msp = (tile & 1) ? ms1 : ms0;

        uint4 pv0, pv1;
        unsigned pm = 0;
        if (tile < 31) {
            const __half* vsrc = &vhead[(tile + 1) * 128 * 32];
            pv0 = *(const uint4*)&vsrc[pr * 32 + pc8];
            pv1 = *(const uint4*)&vsrc[(pr + 64) * 32 + pc8];
            if (tid < 128) pm = g_mask[n0 + (tid >> 2)][(tile + 1) * 4 + (tid & 3)];
        }

        float c[4][4];
#pragma unroll
        for (int s = 0; s < 4; s++)
#pragma unroll
            for (int j = 0; j < 4; j++) c[s][j] = 0.f;
#pragma unroll
        for (int kc = 0; kc < 2; kc++) {
            unsigned a[4];
            LDSM_X4(a, qa_base + kc * 32);
#pragma unroll
            for (int subp = 0; subp < 2; subp++) {
                unsigned b[4];
                LDSM_X4(b, vb0 + voff + subp * 1280 + kc * 32);
                mma_f16(c[2 * subp], a[0], a[1], a[2], a[3], b[0], b[1]);
                mma_f16(c[2 * subp + 1], a[0], a[1], a[2], a[3], b[2], b[3]);
            }
        }

        const unsigned w0 = msp[r0 * 4 + cw];
        const unsigned w1 = msp[r1 * 4 + cw];
#pragma unroll
        for (int sub = 0; sub < 4; sub++) {
            int sh = sub * 8 + 2 * tq;
            float e0 = ((w0 >> sh) & 1u) ? ex2f(fmaf(c[sub][0], EXS, lg0)) : 0.f;
            float e1 = ((w0 >> sh) & 2u) ? ex2f(fmaf(c[sub][1], EXS, lg0)) : 0.f;
            float e2 = ((w1 >> sh) & 1u) ? ex2f(fmaf(c[sub][2], EXS, lg1)) : 0.f;
            float e3 = ((w1 >> sh) & 2u) ? ex2f(fmaf(c[sub][3], EXS, lg1)) : 0.f;
            __stcs((float2*)(a0row + tile * 128 + sub * 8), make_float2(e0, e1));
            __stcs((float2*)(a1row + tile * 128 + sub * 8), make_float2(e2, e3));
        }

        if (tile < 31) {
            __half* vd = (tile & 1) ? vs0 : vs1;
            unsigned* md = (tile & 1) ? ms0 : ms1;
            *(uint4*)&vd[pr * 40 + pc8] = pv0;
            *(uint4*)&vd[(pr + 64) * 40 + pc8] = pv1;
            if (tid < 128) md[tid] = pm;
        }
        __syncthreads();
    }
}

// ---------------- launch ----------------
extern "C" void kernel_launch(void* const* d_in, const int* in_sizes, int n_in,
                              void* d_out, int out_size) {
    (void)in_sizes; (void)n_in; (void)out_size;
    const float* x   = (const float*)d_in[0];
    const int*   Adj = (const int*)d_in[1];
    const float* wq  = (const float*)d_in[2];
    const float* bq  = (const float*)d_in[3];
    // wk (d_in[4], d_in[5]) unused: reference has the q@v^T bug
    const float* wv  = (const float*)d_in[6];
    const float* bv  = (const float*)d_in[7];
    const float* wo  = (const float*)d_in[8];
    const float* bo  = (const float*)d_in[9];
    float* out  = (float*)d_out;
    float* attn = out + (size_t)NN * HID;

    cudaFuncSetAttribute(attn_phase1_kernel,
                         cudaFuncAttributeMaxDynamicSharedMemorySize, SMEM_P1);
    cudaFuncSetAttribute(attn_phase2_kernel,
                         cudaFuncAttributeMaxDynamicSharedMemorySize, SMEM_P2);

    prep_kernel<<<65536 + 2432, 256>>>(Adj, x, wq, wv, wo);          // #1
    gemm16_qv_kernel<<<dim3(32, 4, 2), 256>>>(bq, bv);               // #2
    attn_phase1_kernel<<<dim3(64, 8), 256, SMEM_P1>>>();             // #3
    attn_phase2_kernel<<<dim3(128, 8), 256, SMEM_P2>>>(attn);        // #4 <- profiled
    gemm16_o_kernel<<<dim3(32, 4), 256>>>(bo, out);                  // #5
}

// round 16
// speedup vs baseline: 1.1486x; 1.0101x over previous
#include <cuda_runtime.h>
#include <cuda_fp16.h>
#include <cstdint>

#define NN 4096
#define HID 256
#define NHEADS 8
#define HEADD 32
#define EXS 0.2550390270190456f   // (1/sqrt(32)) * log2(e)

// ---------------- scratch (static device globals; no allocation) ----------------
__device__ __half   g_q[NHEADS][NN][HEADD];     // fp16 q, head-major
__device__ __half   g_v[NHEADS][NN][HEADD];     // fp16 v, head-major
__device__ __half   g_xh[NN * HID];             // fp16 x
__device__ __half   g_wqh[HID * HID];
__device__ __half   g_wvh[HID * HID];
__device__ __half   g_woh[HID * HID];
__device__ __half   g_obh[NN * HID];            // fp16 normalized attn@v
__device__ float    g_inv[NHEADS][NN];          // 1/rowsum
__device__ unsigned g_mask[NN][NN / 32];        // Adj packed to bits

// ---------------- helpers ----------------
__device__ __forceinline__ uint32_t smem_u32(const void* p) {
    uint32_t a;
    asm("{ .reg .u64 t; cvta.to.shared.u64 t, %1; cvt.u32.u64 %0, t; }" : "=r"(a) : "l"(p));
    return a;
}
__device__ __forceinline__ float ex2f(float x) {
    float y;
    asm("ex2.approx.f32 %0, %1;" : "=f"(y) : "f"(x));
    return y;
}
__device__ __forceinline__ void mma_f16(float c[4],
                                        unsigned a0, unsigned a1, unsigned a2, unsigned a3,
                                        unsigned b0, unsigned b1) {
    asm volatile(
        "mma.sync.aligned.m16n8k16.row.col.f32.f16.f16.f32 "
        "{%0,%1,%2,%3},{%4,%5,%6,%7},{%8,%9},{%0,%1,%2,%3};\n"
        : "+f"(c[0]), "+f"(c[1]), "+f"(c[2]), "+f"(c[3])
        : "r"(a0), "r"(a1), "r"(a2), "r"(a3), "r"(b0), "r"(b1));
}
#define LDSM_X4(d, addr) \
    asm volatile("ldmatrix.sync.aligned.m8n8.x4.shared.b16 {%0,%1,%2,%3}, [%4];" \
        : "=r"((d)[0]), "=r"((d)[1]), "=r"((d)[2]), "=r"((d)[3]) : "r"(addr))
#define LDSM_X4T(d, addr) \
    asm volatile("ldmatrix.sync.aligned.m8n8.x4.trans.shared.b16 {%0,%1,%2,%3}, [%4];" \
        : "=r"((d)[0]), "=r"((d)[1]), "=r"((d)[2]), "=r"((d)[3]) : "r"(addr))
__device__ __forceinline__ unsigned h2u(__half2 h) {
    return *reinterpret_cast<unsigned*>(&h);
}

// ---------------- kernel 1: pack Adj -> bitmask AND fp32->fp16 conversions ----------------
__global__ void prep_kernel(const int* __restrict__ Adj, const float* __restrict__ x,
                            const float* __restrict__ wq, const float* __restrict__ wv,
                            const float* __restrict__ wo) {
    int b = blockIdx.x;
    if (b < 65536) {
        int t = b * 256 + threadIdx.x;
        int n = t >> 12;
        int m = t & (NN - 1);
        unsigned bit = (Adj[(size_t)t] != 0) ? 1u : 0u;
        unsigned word = __ballot_sync(0xffffffffu, bit);
        if ((m & 31) == 0) g_mask[n][m >> 5] = word;
    } else {
        int i = (b - 65536) * 256 + threadIdx.x;   // half2 index
        if (i < 524288) {
            float2 f = ((const float2*)x)[i];
            ((__half2*)g_xh)[i] = __floats2half2_rn(f.x, f.y);
        } else if (i < 557056) {
            int j = i - 524288;
            float2 f = ((const float2*)wq)[j];
            ((__half2*)g_wqh)[j] = __floats2half2_rn(f.x, f.y);
        } else if (i < 589824) {
            int j = i - 557056;
            float2 f = ((const float2*)wv)[j];
            ((__half2*)g_wvh)[j] = __floats2half2_rn(f.x, f.y);
        } else {
            int j = i - 589824;
            float2 f = ((const float2*)wo)[j];
            ((__half2*)g_woh)[j] = __floats2half2_rn(f.x, f.y);
        }
    }
}

// ---------------- tensor-core projection GEMMs ----------------
__global__ __launch_bounds__(256, 2) void gemm16_qv_kernel(const float* __restrict__ bq,
                                                           const float* __restrict__ bv) {
    __shared__ __half xs[128 * 72];
    __shared__ __half ws[64 * 72];
    const int tid = threadIdx.x, warp = tid >> 5, lane = tid & 31;
    const int g = lane >> 2, tq = lane & 3;
    const int li = lane >> 3, lj = lane & 7;
    const int m0 = blockIdx.x * 128, o0 = blockIdx.y * 64;
    const __half* A = g_xh;
    const __half* B = blockIdx.z ? g_wvh : g_wqh;
    const float* bias = blockIdx.z ? bv : bq;
    __half* dst = blockIdx.z ? &g_v[0][0][0] : &g_q[0][0][0];

    const uint32_t xa = smem_u32(xs) + ((16 * warp + (li & 1) * 8 + lj) * 72 + (li >> 1) * 8) * 2;
    const uint32_t wb = smem_u32(ws) + (((li >> 1) * 8 + lj) * 72 + (li & 1) * 8) * 2;

    float acc[8][4];
#pragma unroll
    for (int s = 0; s < 8; s++)
#pragma unroll
        for (int j = 0; j < 4; j++) acc[s][j] = 0.f;

    for (int kb = 0; kb < HID; kb += 64) {
        __syncthreads();
#pragma unroll
        for (int i = 0; i < 4; i++) {
            int idx = tid + i * 256;
            int r = idx >> 3, c8 = (idx & 7) * 8;
            *(uint4*)&xs[r * 72 + c8] = *(const uint4*)&A[(size_t)(m0 + r) * HID + kb + c8];
        }
#pragma unroll
        for (int i = 0; i < 2; i++) {
            int idx = tid + i * 256;
            int r = idx >> 3, c8 = (idx & 7) * 8;
            *(uint4*)&ws[r * 72 + c8] = *(const uint4*)&B[(size_t)(o0 + r) * HID + kb + c8];
        }
        __syncthreads();
#pragma unroll
        for (int kc = 0; kc < 4; kc++) {
            unsigned a[4];
            LDSM_X4(a, xa + kc * 32);
#pragma unroll
            for (int subp = 0; subp < 4; subp++) {
                unsigned b[4];
                LDSM_X4(b, wb + subp * 2304 + kc * 32);
                mma_f16(acc[2 * subp], a[0], a[1], a[2], a[3], b[0], b[1]);
                mma_f16(acc[2 * subp + 1], a[0], a[1], a[2], a[3], b[2], b[3]);
            }
        }
    }
    const int r0 = m0 + 16 * warp + g, r1 = r0 + 8;
#pragma unroll
    for (int sub = 0; sub < 8; sub++) {
        int o = o0 + sub * 8 + 2 * tq;
        float b0 = bias[o], b1 = bias[o + 1];
        int hd = o >> 5, cc = o & 31;
        *(__half2*)&dst[((size_t)hd * NN + r0) * HEADD + cc] =
            __floats2half2_rn(acc[sub][0] + b0, acc[sub][1] + b1);
        *(__half2*)&dst[((size_t)hd * NN + r1) * HEADD + cc] =
            __floats2half2_rn(acc[sub][2] + b0, acc[sub][3] + b1);
    }
}

__global__ __launch_bounds__(256, 2) void gemm16_o_kernel(const float* __restrict__ bias,
                                                          float* __restrict__ Out) {
    __shared__ __half xs[128 * 72];
    __shared__ __half ws[64 * 72];
    const int tid = threadIdx.x, warp = tid >> 5, lane = tid & 31;
    const int g = lane >> 2, tq = lane & 3;
    const int li = lane >> 3, lj = lane & 7;
    const int m0 = blockIdx.x * 128, o0 = blockIdx.y * 64;
    const __half* A = g_obh;
    const __half* B = g_woh;

    const uint32_t xa = smem_u32(xs) + ((16 * warp + (li & 1) * 8 + lj) * 72 + (li >> 1) * 8) * 2;
    const uint32_t wb = smem_u32(ws) + (((li >> 1) * 8 + lj) * 72 + (li & 1) * 8) * 2;

    float acc[8][4];
#pragma unroll
    for (int s = 0; s < 8; s++)
#pragma unroll
        for (int j = 0; j < 4; j++) acc[s][j] = 0.f;

    for (int kb = 0; kb < HID; kb += 64) {
        __syncthreads();
#pragma unroll
        for (int i = 0; i < 4; i++) {
            int idx = tid + i * 256;
            int r = idx >> 3, c8 = (idx & 7) * 8;
            *(uint4*)&xs[r * 72 + c8] = *(const uint4*)&A[(size_t)(m0 + r) * HID + kb + c8];
        }
#pragma unroll
        for (int i = 0; i < 2; i++) {
            int idx = tid + i * 256;
            int r = idx >> 3, c8 = (idx & 7) * 8;
            *(uint4*)&ws[r * 72 + c8] = *(const uint4*)&B[(size_t)(o0 + r) * HID + kb + c8];
        }
        __syncthreads();
#pragma unroll
        for (int kc = 0; kc < 4; kc++) {
            unsigned a[4];
            LDSM_X4(a, xa + kc * 32);
#pragma unroll
            for (int subp = 0; subp < 4; subp++) {
                unsigned b[4];
                LDSM_X4(b, wb + subp * 2304 + kc * 32);
                mma_f16(acc[2 * subp], a[0], a[1], a[2], a[3], b[0], b[1]);
                mma_f16(acc[2 * subp + 1], a[0], a[1], a[2], a[3], b[2], b[3]);
            }
        }
    }
    const int r0 = m0 + 16 * warp + g, r1 = r0 + 8;
#pragma unroll
    for (int sub = 0; sub < 8; sub++) {
        int o = o0 + sub * 8 + 2 * tq;
        float b0 = bias[o], b1 = bias[o + 1];
        *(float2*)&Out[(size_t)r0 * HID + o] = make_float2(acc[sub][0] + b0, acc[sub][1] + b1);
        *(float2*)&Out[(size_t)r1 * HID + o] = make_float2(acc[sub][2] + b0, acc[sub][3] + b1);
    }
}

// ---------------- attention phase 1: M=32 CTAs, rowsums + O, 3 CTAs/SM ----------------
constexpr int P1_QS  = 0;         // [32][40] half   (2560 B)
constexpr int P1_VS0 = 2560;      // [128][40] half  (10240 B)
constexpr int P1_VS1 = 12800;     // [128][40] half  (10240 B)
constexpr int P1_MS0 = 23040;     // [32][4] unsigned (512 B)
constexpr int P1_MS1 = 23552;     // [32][4] unsigned (512 B)
constexpr int P1_RS  = 24064;     // [4][32] float    (512 B)
constexpr int SMEM_P1 = 24576;
// O-partial staging obr[4][32][34] floats (17408 B) overlays P1_VS0.. after the loop

__global__ __launch_bounds__(256, 3) void attn_phase1_kernel() {
    extern __shared__ char sm[];
    __half* qs  = (__half*)(sm + P1_QS);
    __half* vs0 = (__half*)(sm + P1_VS0);
    __half* vs1 = (__half*)(sm + P1_VS1);
    unsigned* ms0 = (unsigned*)(sm + P1_MS0);
    unsigned* ms1 = (unsigned*)(sm + P1_MS1);
    float* rsA = (float*)(sm + P1_RS);
    const uint32_t sb = smem_u32(sm);

    const int head = blockIdx.y;
    const int n0 = blockIdx.x * 32;
    const int tid = threadIdx.x;
    const int wid = tid >> 5, lane = tid & 31;
    const int rw = wid & 1, cw = wid >> 1;        // 2 row-groups x 4 key-slices(32)
    const int g = lane >> 2, tq = lane & 3;
    const int li = lane >> 3, lj = lane & 7;
    const int r0 = rw * 16 + g;                   // local rows 0..31
    const int r1 = r0 + 8;

    const uint32_t qa_base = sb + P1_QS + ((rw * 16 + (li & 1) * 8 + lj) * 40 + (li >> 1) * 8) * 2;
    const uint32_t vb0 = sb + P1_VS0 + ((cw * 32 + (li >> 1) * 8 + lj) * 40 + (li & 1) * 8) * 2;
    const uint32_t vt0 = sb + P1_VS0 + ((cw * 32 + (li & 1) * 8 + lj) * 40 + (li >> 1) * 8) * 2;

    const __half* vhead = &g_v[head][0][0];
    const int pr = tid >> 2, pc8 = (tid & 3) * 8;

    if (tid < 128) {
        int r = tid >> 2, c8 = (tid & 3) * 8;
        *(uint4*)&qs[r * 40 + c8] = *(const uint4*)&g_q[head][n0 + r][c8];
        ms0[tid] = g_mask[n0 + (tid >> 2)][tid & 3];
    }
#pragma unroll
    for (int i = 0; i < 2; i++)
        *(uint4*)&vs0[(pr + i * 64) * 40 + pc8] = *(const uint4*)&vhead[(pr + i * 64) * 32 + pc8];
    __syncthreads();

    float oacc[4][4];
#pragma unroll
    for (int i = 0; i < 4; i++)
#pragma unroll
        for (int j = 0; j < 4; j++) oacc[i][j] = 0.f;
    float rs0 = 0.f, rs1 = 0.f;

    for (int tile = 0; tile < 32; tile++) {
        const uint32_t voff = (tile & 1) ? 10240u : 0u;
        unsigned* msp = (tile & 1) ? ms1 : ms0;

        uint4 pv0, pv1;
        unsigned pm = 0;
        if (tile < 31) {
            const __half* vsrc = &vhead[(tile + 1) * 128 * 32];
            pv0 = *(const uint4*)&vsrc[pr * 32 + pc8];
            pv1 = *(const uint4*)&vsrc[(pr + 64) * 32 + pc8];
            if (tid < 128) pm = g_mask[n0 + (tid >> 2)][(tile + 1) * 4 + (tid & 3)];
        }

        // MMA1: S(16x32 per warp), keys cw*32..+31
        float c[4][4];
#pragma unroll
        for (int s = 0; s < 4; s++)
#pragma unroll
            for (int j = 0; j < 4; j++) c[s][j] = 0.f;
#pragma unroll
        for (int kc = 0; kc < 2; kc++) {
            unsigned a[4];
            LDSM_X4(a, qa_base + kc * 32);
#pragma unroll
            for (int subp = 0; subp < 2; subp++) {
                unsigned b[4];
                LDSM_X4(b, vb0 + voff + subp * 1280 + kc * 32);
                mma_f16(c[2 * subp], a[0], a[1], a[2], a[3], b[0], b[1]);
                mma_f16(c[2 * subp + 1], a[0], a[1], a[2], a[3], b[2], b[3]);
            }
        }

        // mask + exp -> rowsum; pack fp16 A-frags
        const unsigned w0 = msp[r0 * 4 + cw];
        const unsigned w1 = msp[r1 * 4 + cw];
        unsigned ah0[4], ah1[4];
#pragma unroll
        for (int sub = 0; sub < 4; sub++) {
            int sh = sub * 8 + 2 * tq;
            float e0 = ((w0 >> sh) & 1u) ? ex2f(c[sub][0] * EXS) : 0.f;
            float e1 = ((w0 >> sh) & 2u) ? ex2f(c[sub][1] * EXS) : 0.f;
            float e2 = ((w1 >> sh) & 1u) ? ex2f(c[sub][2] * EXS) : 0.f;
            float e3 = ((w1 >> sh) & 2u) ? ex2f(c[sub][3] * EXS) : 0.f;
            rs0 += e0 + e1;
            rs1 += e2 + e3;
            ah0[sub] = h2u(__floats2half2_rn(e0, e1));
            ah1[sub] = h2u(__floats2half2_rn(e2, e3));
        }

        // MMA2: O(16x32) += E(16x32) @ V(32x32) over this warp's key slice
#pragma unroll
        for (int kc2 = 0; kc2 < 2; kc2++) {
            unsigned a0 = ah0[2 * kc2], a1 = ah1[2 * kc2];
            unsigned a2 = ah0[2 * kc2 + 1], a3 = ah1[2 * kc2 + 1];
#pragma unroll
            for (int dsp = 0; dsp < 2; dsp++) {
                unsigned t[4];
                LDSM_X4T(t, vt0 + voff + kc2 * 1280 + dsp * 32);
                mma_f16(oacc[2 * dsp], a0, a1, a2, a3, t[0], t[1]);
                mma_f16(oacc[2 * dsp + 1], a0, a1, a2, a3, t[2], t[3]);
            }
        }

        if (tile < 31) {
            __half* vd = (tile & 1) ? vs0 : vs1;
            unsigned* md = (tile & 1) ? ms0 : ms1;
            *(uint4*)&vd[pr * 40 + pc8] = pv0;
            *(uint4*)&vd[(pr + 64) * 40 + pc8] = pv1;
            if (tid < 128) md[tid] = pm;
        }
        __syncthreads();
    }

    // rowsum: quad butterfly (partial over 32-key slice) -> smem -> full sum
    rs0 += __shfl_xor_sync(0xffffffffu, rs0, 1);
    rs0 += __shfl_xor_sync(0xffffffffu, rs0, 2);
    rs1 += __shfl_xor_sync(0xffffffffu, rs1, 1);
    rs1 += __shfl_xor_sync(0xffffffffu, rs1, 2);
    if (tq == 0) {
        rsA[cw * 32 + r0] = rs0;
        rsA[cw * 32 + r1] = rs1;
    }
    __syncthreads();
    const float inv0 = 1.0f / (rsA[r0] + rsA[32 + r0] + rsA[64 + r0] + rsA[96 + r0]);
    const float inv1 = 1.0f / (rsA[r1] + rsA[32 + r1] + rsA[64 + r1] + rsA[96 + r1]);
    if (tid < 32)
        g_inv[head][n0 + tid] =
            1.0f / (rsA[tid] + rsA[32 + tid] + rsA[64 + tid] + rsA[96 + tid]);

    // O cross-slice reduce: all warps stage partials (stride-34 pad), cw==0 warps sum
    float* obr = (float*)(sm + P1_VS0);   // [4][32][34]
#pragma unroll
    for (int ds = 0; ds < 4; ds++) {
        int col = ds * 8 + 2 * tq;
        *(float2*)&obr[cw * 1088 + r0 * 34 + col] = make_float2(oacc[ds][0], oacc[ds][1]);
        *(float2*)&obr[cw * 1088 + r1 * 34 + col] = make_float2(oacc[ds][2], oacc[ds][3]);
    }
    __syncthreads();
    if (cw == 0) {
#pragma unroll
        for (int ds = 0; ds < 4; ds++) {
            int col = ds * 8 + 2 * tq;
            float sx0 = 0.f, sy0 = 0.f, sx1 = 0.f, sy1 = 0.f;
#pragma unroll
            for (int k = 0; k < 4; k++) {
                float2 p0 = *(const float2*)&obr[k * 1088 + r0 * 34 + col];
                float2 p1 = *(const float2*)&obr[k * 1088 + r1 * 34 + col];
                sx0 += p0.x; sy0 += p0.y;
                sx1 += p1.x; sy1 += p1.y;
            }
            *(__half2*)&g_obh[(size_t)(n0 + r0) * HID + head * 32 + col] =
                __floats2half2_rn(sx0 * inv0, sy0 * inv0);
            *(__half2*)&g_obh[(size_t)(n0 + r1) * HID + head * 32 + col] =
                __floats2half2_rn(sx1 * inv1, sy1 * inv1);
        }
    }
}

// ---------------- attention phase 2: M=32 CTAs, shuffle-packed STG.128 attn stream ----------------
constexpr int P2_QS  = 0;         // [32][40] half   (2560 B)
constexpr int P2_VS0 = 2560;      // [128][40] half  (10240 B)
constexpr int P2_VS1 = 12800;     // [128][40] half  (10240 B)
constexpr int P2_MS0 = 23040;     // [32][4] unsigned (512 B)
constexpr int P2_MS1 = 23552;     // [32][4] unsigned (512 B)
constexpr int SMEM_P2 = 24576;

__global__ __launch_bounds__(256, 4) void attn_phase2_kernel(float* __restrict__ attn_out) {
    extern __shared__ char sm[];
    __half* qs  = (__half*)(sm + P2_QS);
    __half* vs0 = (__half*)(sm + P2_VS0);
    __half* vs1 = (__half*)(sm + P2_VS1);
    unsigned* ms0 = (unsigned*)(sm + P2_MS0);
    unsigned* ms1 = (unsigned*)(sm + P2_MS1);
    const uint32_t sb = smem_u32(sm);

    const int head = blockIdx.y;
    const int n0 = blockIdx.x * 32;
    const int tid = threadIdx.x;
    const int wid = tid >> 5, lane = tid & 31;
    const int rw = wid & 1, cw = wid >> 1;        // 2 row-groups x 4 col-groups(32)
    const int g = lane >> 2, tq = lane & 3;
    const int li = lane >> 3, lj = lane & 7;
    const int r0 = rw * 16 + g;
    const int r1 = r0 + 8;

    const uint32_t qa_base = sb + P2_QS + ((rw * 16 + (li & 1) * 8 + lj) * 40 + (li >> 1) * 8) * 2;
    const uint32_t vb0 = sb + P2_VS0 + ((cw * 32 + (li >> 1) * 8 + lj) * 40 + (li & 1) * 8) * 2;

    const __half* vhead = &g_v[head][0][0];
    const int pr = tid >> 2, pc8 = (tid & 3) * 8;

    if (tid < 128) {
        int r = tid >> 2, c8 = (tid & 3) * 8;
        *(uint4*)&qs[r * 40 + c8] = *(const uint4*)&g_q[head][n0 + r][c8];
        ms0[tid] = g_mask[n0 + (tid >> 2)][tid & 3];
    }
#pragma unroll
    for (int i = 0; i < 2; i++)
        *(uint4*)&vs0[(pr + i * 64) * 40 + pc8] = *(const uint4*)&vhead[(pr + i * 64) * 32 + pc8];

    const float lg0 = __log2f(g_inv[head][n0 + r0]);
    const float lg1 = __log2f(g_inv[head][n0 + r1]);
    __syncthreads();

    // shuffle-packed store coords: lane owns cols 16s + cb4 (4 consecutive floats)
    const int cb4 = (tq & 1) * 8 + (tq >> 1) * 4;
    float* a0base = &attn_out[((size_t)(head * NN + n0 + r0)) * NN + cw * 32];
    float* a1base = &attn_out[((size_t)(head * NN + n0 + r1)) * NN + cw * 32];

    for (int tile = 0; tile < 32; tile++) {
        const uint32_t voff = (tile & 1) ? 10240u : 0u;
        unsigned* msp = (tile & 1) ? ms1 : ms0;

        uint4 pv0, pv1;
        unsigned pm = 0;
        if (tile < 31) {
            const __half* vsrc = &vhead[(tile + 1) * 128 * 32];
            pv0 = *(const uint4*)&vsrc[pr * 32 + pc8];
            pv1 = *(const uint4*)&vsrc[(pr + 64) * 32 + pc8];
            if (tid < 128) pm = g_mask[n0 + (tid >> 2)][(tile + 1) * 4 + (tid & 3)];
        }

        float c[4][4];
#pragma unroll
        for (int s = 0; s < 4; s++)
#pragma unroll
            for (int j = 0; j < 4; j++) c[s][j] = 0.f;
#pragma unroll
        for (int kc = 0; kc < 2; kc++) {
            unsigned a[4];
            LDSM_X4(a, qa_base + kc * 32);
#pragma unroll
            for (int subp = 0; subp < 2; subp++) {
                unsigned b[4];
                LDSM_X4(b, vb0 + voff + subp * 1280 + kc * 32);
                mma_f16(c[2 * subp], a[0], a[1], a[2], a[3], b[0], b[1]);
                mma_f16(c[2 * subp + 1], a[0], a[1], a[2], a[3], b[2], b[3]);
            }
        }

        const unsigned w0 = msp[r0 * 4 + cw];
        const unsigned w1 = msp[r1 * 4 + cw];
#pragma unroll
        for (int s = 0; s < 2; s++) {
            // sub pair {2s, 2s+1}: A = cols 16s+2tq(+1), B = cols 16s+8+2tq(+1)
            int shA = 2 * s * 8 + 2 * tq;
            int shB = shA + 8;
            float2 A0, B0, A1, B1;
            A0.x = ((w0 >> shA) & 1u) ? ex2f(fmaf(c[2 * s][0], EXS, lg0)) : 0.f;
            A0.y = ((w0 >> shA) & 2u) ? ex2f(fmaf(c[2 * s][1], EXS, lg0)) : 0.f;
            A1.x = ((w1 >> shA) & 1u) ? ex2f(fmaf(c[2 * s][2], EXS, lg1)) : 0.f;
            A1.y = ((w1 >> shA) & 2u) ? ex2f(fmaf(c[2 * s][3], EXS, lg1)) : 0.f;
            B0.x = ((w0 >> shB) & 1u) ? ex2f(fmaf(c[2 * s + 1][0], EXS, lg0)) : 0.f;
            B0.y = ((w0 >> shB) & 2u) ? ex2f(fmaf(c[2 * s + 1][1], EXS, lg0)) : 0.f;
            B1.x = ((w1 >> shB) & 1u) ? ex2f(fmaf(c[2 * s + 1][2], EXS, lg1)) : 0.f;
            B1.y = ((w1 >> shB) & 2u) ? ex2f(fmaf(c[2 * s + 1][3], EXS, lg1)) : 0.f;

            // quad exchange with lane tq^1: even lanes keep A + recv partner's A,
            // odd lanes recv partner's B + keep B
            float sx0 = (tq & 1) ? A0.x : B0.x;
            float sy0 = (tq & 1) ? A0.y : B0.y;
            float sx1 = (tq & 1) ? A1.x : B1.x;
            float sy1 = (tq & 1) ? A1.y : B1.y;
            float rx0 = __shfl_xor_sync(0xffffffffu, sx0, 1);
            float ry0 = __shfl_xor_sync(0xffffffffu, sy0, 1);
            float rx1 = __shfl_xor_sync(0xffffffffu, sx1, 1);
            float ry1 = __shfl_xor_sync(0xffffffffu, sy1, 1);
            float4 o0 = (tq & 1) ? make_float4(rx0, ry0, B0.x, B0.y)
                                 : make_float4(A0.x, A0.y, rx0, ry0);
            float4 o1 = (tq & 1) ? make_float4(rx1, ry1, B1.x, B1.y)
                                 : make_float4(A1.x, A1.y, rx1, ry1);
            int cb = s * 16 + cb4;
            __stcs((float4*)(a0base + tile * 128 + cb), o0);
            __stcs((float4*)(a1base + tile * 128 + cb), o1);
        }

        if (tile < 31) {
            __half* vd = (tile & 1) ? vs0 : vs1;
            unsigned* md = (tile & 1) ? ms0 : ms1;
            *(uint4*)&vd[pr * 40 + pc8] = pv0;
            *(uint4*)&vd[(pr + 64) * 40 + pc8] = pv1;
            if (tid < 128) md[tid] = pm;
        }
        __syncthreads();
    }
}

// ---------------- launch ----------------
extern "C" void kernel_launch(void* const* d_in, const int* in_sizes, int n_in,
                              void* d_out, int out_size) {
    (void)in_sizes; (void)n_in; (void)out_size;
    const float* x   = (const float*)d_in[0];
    const int*   Adj = (const int*)d_in[1];
    const float* wq  = (const float*)d_in[2];
    const float* bq  = (const float*)d_in[3];
    // wk (d_in[4], d_in[5]) unused: reference has the q@v^T bug
    const float* wv  = (const float*)d_in[6];
    const float* bv  = (const float*)d_in[7];
    const float* wo  = (const float*)d_in[8];
    const float* bo  = (const float*)d_in[9];
    float* out  = (float*)d_out;
    float* attn = out + (size_t)NN * HID;

    cudaFuncSetAttribute(attn_phase1_kernel,
                         cudaFuncAttributeMaxDynamicSharedMemorySize, SMEM_P1);
    cudaFuncSetAttribute(attn_phase2_kernel,
                         cudaFuncAttributeMaxDynamicSharedMemorySize, SMEM_P2);

    prep_kernel<<<65536 + 2432, 256>>>(Adj, x, wq, wv, wo);          // #1
    gemm16_qv_kernel<<<dim3(32, 4, 2), 256>>>(bq, bv);               // #2
    attn_phase1_kernel<<<dim3(128, 8), 256, SMEM_P1>>>();            // #3
    attn_phase2_kernel<<<dim3(128, 8), 256, SMEM_P2>>>(attn);        // #4 <- profiled
    gemm16_o_kernel<<<dim3(32, 4), 256>>>(bo, out);                  // #5
}